// round 14
// baseline (speedup 1.0000x reference)
#include <cuda_runtime.h>

#define NN 50000
#define NE 800000
#define HH 64

// Scratch (no runtime allocation allowed)
__device__ __align__(16) float g_p[NN * HH];      // nf @ W1a^T
__device__ __align__(16) float g_q[NN * HH];      // nf @ W1b^T
__device__ __align__(16) float g_efs[NN * 16];    // per-dst ef sums (RED in scatter)

// CSR build scratch
__device__ int  g_cnt[NN];      // zero at load; re-zeroed by scan1 each run
__device__ int  g_off[NN + 1];
__device__ int  g_cur[NN];
__device__ int  g_bsum[64];
__device__ int  g_esrc[NE];     // src, sorted by dst

// Pre-transposed weights (filled by hist_kernel block 0)
__device__ __align__(16) float g_WpqT[32 * 128];  // [k][j]: j<64 -> W1a, j>=64 -> W1b
__device__ __align__(16) float g_W1dT[64 * 64];   // [k][j] = W1[j][80+k]
__device__ __align__(16) float g_W1cT[16 * 64];   // [k][j] = W1[j][64+k]
__device__ __align__(16) float g_W2T[64 * 64];    // [j][i] = W2[i][j]

__device__ __forceinline__ void fma4(float4& a, float x, const float4& wv) {
    a.x = fmaf(x, wv.x, a.x);
    a.y = fmaf(x, wv.y, a.y);
    a.z = fmaf(x, wv.z, a.z);
    a.w = fmaf(x, wv.w, a.w);
}

__device__ __forceinline__ void add4(float4& a, const float4& b) {
    a.x += b.x; a.y += b.y; a.z += b.z; a.w += b.w;
}

// ---------------------------------------------------------------------------
// Launch 1: histogram of dst + zero g_efs; block 0 also transposes weights.
// Relies on g_cnt == 0 on entry (zero-init at load; scan1 re-zeroes each run).
// ---------------------------------------------------------------------------
__global__ __launch_bounds__(256) void hist_kernel(
    const int* __restrict__ dst, const float* __restrict__ W1,
    const float* __restrict__ W2, int E)
{
    int tid = blockIdx.x * blockDim.x + threadIdx.x;
    int stride = gridDim.x * blockDim.x;

    float4* efs4 = reinterpret_cast<float4*>(g_efs);
    float4 z = make_float4(0.f, 0.f, 0.f, 0.f);
    for (int i = tid; i < NN * 4; i += stride) efs4[i] = z;

    if (tid < E) atomicAdd(&g_cnt[__ldg(&dst[tid])], 1);

    if (blockIdx.x == 0) {
        for (int idx = threadIdx.x; idx < 64 * 144; idx += 256) {
            int j = idx / 144, k = idx % 144;
            float w = W1[idx];
            if (k < 32)       g_WpqT[k * 128 + j] = w;
            else if (k < 64)  g_WpqT[(k - 32) * 128 + 64 + j] = w;
            else if (k < 80)  g_W1cT[(k - 64) * 64 + j] = w;
            else              g_W1dT[(k - 80) * 64 + j] = w;
        }
        for (int idx = threadIdx.x; idx < 64 * 64; idx += 256) {
            int i = idx >> 6, j = idx & 63;
            g_W2T[j * 64 + i] = W2[idx];
        }
    }
}

// ---------------------------------------------------------------------------
// Launch 2: per-1024-chunk exclusive scan + chunk totals; re-zero g_cnt.
// ---------------------------------------------------------------------------
__global__ __launch_bounds__(1024) void scan1_kernel()
{
    __shared__ int s[1024];
    int tid = threadIdx.x;
    int idx = blockIdx.x * 1024 + tid;
    int v = 0;
    if (idx < NN) {
        v = g_cnt[idx];
        g_cnt[idx] = 0;          // reset for next run (graph replay invariant)
    }
    s[tid] = v;
    __syncthreads();
    #pragma unroll
    for (int d = 1; d < 1024; d <<= 1) {
        int t = (tid >= d) ? s[tid - d] : 0;
        __syncthreads();
        s[tid] += t;
        __syncthreads();
    }
    if (idx < NN) g_off[idx] = s[tid] - v;   // exclusive (within chunk)
    if (tid == 1023) g_bsum[blockIdx.x] = s[1023];
}

// ---------------------------------------------------------------------------
// Launch 3: add chunk-prefix; fill g_cur. (Must finish before any scatter.)
// ---------------------------------------------------------------------------
__global__ __launch_bounds__(1024) void scan2_kernel(int E)
{
    int b = blockIdx.x, tid = threadIdx.x;
    int idx = b * 1024 + tid;
    int add = 0;
    for (int j = 0; j < b; j++) add += g_bsum[j];   // uniform, tiny
    if (idx < NN) {
        int v = g_off[idx] + add;
        g_off[idx] = v;
        g_cur[idx] = v;
    }
    if (b == 0 && tid == 0) g_off[NN] = E;
}

// ---------------------------------------------------------------------------
// Launch 4 (block-partitioned fusion): scatter | pq GEMM.
//   blocks [0, gs):      scatter src + RED ef sums (L2/latency-bound)
//   blocks [gs, ...):    [p|q] = nf @ [W1a^T|W1b^T], 64-node tile (FMA-bound)
// u GEMM is GONE: W1d is deferred through the segment sum into finalize.
// ---------------------------------------------------------------------------
__global__ __launch_bounds__(256) void fused4_kernel(
    const int* __restrict__ src, const int* __restrict__ dst,
    const float* __restrict__ ef, const float* __restrict__ nf,
    int N, int E, int gs)
{
    __shared__ __align__(16) char smem_raw[24576];
    int b = blockIdx.x;

    if (b < gs) {
        // ---- scatter ----
        int i = b * 256 + threadIdx.x;
        if (i >= E) return;
        int d = __ldg(&dst[i]);
        int pos = atomicAdd(&g_cur[d], 1);
        g_esrc[pos] = __ldg(&src[i]);

        const float4* ef4 = reinterpret_cast<const float4*>(ef);
        float4* efs4 = reinterpret_cast<float4*>(g_efs);
        #pragma unroll
        for (int c = 0; c < 4; c++)
            atomicAdd(&efs4[d * 4 + c], __ldg(&ef4[i * 4 + c]));
        return;
    }

    // ---- pq GEMM: 64 nodes x 128 outputs, K=32, acc[8] ----
    {
        int bid = b - gs;
        float* sW = reinterpret_cast<float*>(smem_raw);            // 32*128 = 16KB
        float* sX = reinterpret_cast<float*>(smem_raw + 16384);    // 64*32  = 8KB

        for (int idx = threadIdx.x; idx < 32 * 128; idx += 256)
            sW[idx] = g_WpqT[idx];

        int n0 = bid * 64;
        const float4* nf4 = reinterpret_cast<const float4*>(nf);
        float4* sX4 = reinterpret_cast<float4*>(sX);
        for (int idx = threadIdx.x; idx < 512; idx += 256) {
            int n = n0 + (idx >> 3);
            sX4[idx] = (n < N) ? __ldg(&nf4[n * 8 + (idx & 7)])
                               : make_float4(0.f, 0.f, 0.f, 0.f);
        }
        __syncthreads();

        int jg = threadIdx.x & 31;
        int ng = threadIdx.x >> 5;
        const float* xb = sX + ng * 8 * 32;
        const float4* sW4 = reinterpret_cast<const float4*>(sW);

        float4 acc[8];
        #pragma unroll
        for (int i = 0; i < 8; i++) acc[i] = make_float4(0.f, 0.f, 0.f, 0.f);

        #pragma unroll 8
        for (int k = 0; k < 32; k++) {
            float4 wv = sW4[k * 32 + jg];
            #pragma unroll
            for (int i = 0; i < 8; i++) fma4(acc[i], xb[i * 32 + k], wv);
        }

        float4* dst4 = (jg < 16) ? reinterpret_cast<float4*>(g_p)
                                 : reinterpret_cast<float4*>(g_q);
        int jj = jg & 15;
        #pragma unroll
        for (int i = 0; i < 8; i++) {
            int n = n0 + ng * 8 + i;
            if (n < N) dst4[n * 16 + jj] = acc[i];
        }
    }
}

// ---------------------------------------------------------------------------
// Launch 5: fused gather + finalize with deferred W1d.
// Warp = 2 edge slots x 16 float4 lanes; gathers mh = sum h[src] directly.
// y = W1d@mh + p + deg*q + W1c@efs; relu; staged 4-node W2 GEMM.
// ---------------------------------------------------------------------------
__global__ __launch_bounds__(256) void gather_finalize_kernel(
    const float* __restrict__ h, float* __restrict__ out, int N)
{
    __shared__ float sW1cT[16 * 64];                 // 4KB
    __shared__ float sW1dT[64 * 64];                 // 16KB
    __shared__ float sW2T[64 * 64];                  // 16KB
    __shared__ __align__(16) float sY[8][4 * 64];    // 8KB
    __shared__ float sEf[8][4 * 16];                 // 2KB

    for (int idx = threadIdx.x; idx < 16 * 64; idx += 256) sW1cT[idx] = g_W1cT[idx];
    for (int idx = threadIdx.x; idx < 64 * 64; idx += 256) {
        sW1dT[idx] = g_W1dT[idx];
        sW2T[idx]  = g_W2T[idx];
    }
    __syncthreads();

    int lane = threadIdx.x & 31;
    int warp = threadIdx.x >> 5;
    int slot = lane >> 4;          // 0 or 1
    int f4   = lane & 15;          // float4 index within 64-float row
    int gw = (blockIdx.x * blockDim.x + threadIdx.x) >> 5;
    int nb = gw * 4;
    if (nb >= N) return;
    int cnt = min(4, N - nb);

    const float4* h4 = reinterpret_cast<const float4*>(h);
    float dgv[4];

    // ---- phase 1: per node, gather mh = sum h[src] into sY; load efs ----
    for (int m = 0; m < cnt; m++) {
        int n = nb + m;
        int off0 = __ldg(&g_off[n]);
        int off1 = __ldg(&g_off[n + 1]);
        dgv[m] = (float)(off1 - off0);

        float4 acc = make_float4(0.f, 0.f, 0.f, 0.f);

        int i = off0;
        for (; i + 8 <= off1; i += 8) {
            int sA = __ldg(&g_esrc[i     + slot]);
            int sB = __ldg(&g_esrc[i + 2 + slot]);
            int sC = __ldg(&g_esrc[i + 4 + slot]);
            int sD = __ldg(&g_esrc[i + 6 + slot]);
            float4 vA = __ldg(&h4[sA * 16 + f4]);
            float4 vB = __ldg(&h4[sB * 16 + f4]);
            float4 vC = __ldg(&h4[sC * 16 + f4]);
            float4 vD = __ldg(&h4[sD * 16 + f4]);
            add4(acc, vA); add4(acc, vB); add4(acc, vC); add4(acc, vD);
        }
        for (; i + 2 <= off1; i += 2) {
            int s = __ldg(&g_esrc[i + slot]);
            float4 v = __ldg(&h4[s * 16 + f4]);
            add4(acc, v);
        }
        if (i < off1 && slot == 0) {   // odd remainder: slot-0 lanes only
            int s = __ldg(&g_esrc[i]);
            float4 v = __ldg(&h4[s * 16 + f4]);
            add4(acc, v);
        }

        // merge slot 0 + slot 1
        acc.x += __shfl_xor_sync(0xffffffffu, acc.x, 16);
        acc.y += __shfl_xor_sync(0xffffffffu, acc.y, 16);
        acc.z += __shfl_xor_sync(0xffffffffu, acc.z, 16);
        acc.w += __shfl_xor_sync(0xffffffffu, acc.w, 16);

        if (lane < 16) {
            reinterpret_cast<float4*>(&sY[warp][m * 64])[f4] = acc;
            sEf[warp][m * 16 + lane] = __ldg(&g_efs[n * 16 + lane]);
        }
        __syncwarp();
    }

    // ---- phase 2: y = W1d@mh + p + deg*q + W1c@efs (4-node amortized) ----
    float y0[4], y1[4];
    #pragma unroll
    for (int m = 0; m < 4; m++) {
        int n = nb + ((m < cnt) ? m : 0);    // clamp to stay in bounds
        y0[m] = g_p[n * 64 + lane]      + dgv[(m < cnt) ? m : 0] * g_q[n * 64 + lane];
        y1[m] = g_p[n * 64 + lane + 32] + dgv[(m < cnt) ? m : 0] * g_q[n * 64 + lane + 32];
    }
    #pragma unroll
    for (int k = 0; k < 16; k++) {
        float w0 = sW1cT[k * 64 + lane];
        float w1 = sW1cT[k * 64 + lane + 32];
        #pragma unroll
        for (int m = 0; m < 4; m++) {
            float e = sEf[warp][m * 16 + k];
            y0[m] = fmaf(e, w0, y0[m]);
            y1[m] = fmaf(e, w1, y1[m]);
        }
    }
    #pragma unroll
    for (int k = 0; k < 64; k++) {
        float w0 = sW1dT[k * 64 + lane];
        float w1 = sW1dT[k * 64 + lane + 32];
        #pragma unroll
        for (int m = 0; m < 4; m++) {
            float t = sY[warp][m * 64 + k];
            y0[m] = fmaf(t, w0, y0[m]);
            y1[m] = fmaf(t, w1, y1[m]);
        }
    }
    __syncwarp();
    #pragma unroll
    for (int m = 0; m < 4; m++) {
        sY[warp][m * 64 + lane]      = fmaxf(y0[m], 0.f);
        sY[warp][m * 64 + lane + 32] = fmaxf(y1[m], 0.f);
    }
    __syncwarp();

    // ---- phase 3: out = relu(y) @ W2^T ----
    float o0[4] = {0.f, 0.f, 0.f, 0.f};
    float o1[4] = {0.f, 0.f, 0.f, 0.f};
    #pragma unroll
    for (int j = 0; j < 64; j++) {
        float w0 = sW2T[j * 64 + lane];
        float w1 = sW2T[j * 64 + lane + 32];
        #pragma unroll
        for (int m = 0; m < 4; m++) {
            float yj = sY[warp][m * 64 + j];
            o0[m] = fmaf(yj, w0, o0[m]);
            o1[m] = fmaf(yj, w1, o1[m]);
        }
    }

    for (int m = 0; m < cnt; m++) {
        int n = nb + m;
        if (dgv[m] > 0.f) {
            out[n * 64 + lane]      = o0[m];
            out[n * 64 + lane + 32] = o1[m];
        } else {
            out[n * 64 + lane]      = h[n * 64 + lane];
            out[n * 64 + lane + 32] = h[n * 64 + lane + 32];
        }
    }
}

// ---------------------------------------------------------------------------
extern "C" void kernel_launch(void* const* d_in, const int* in_sizes, int n_in,
                              void* d_out, int out_size)
{
    const float* h  = (const float*)d_in[0];
    const float* nf = (const float*)d_in[1];
    const float* ef = (const float*)d_in[2];
    const int*  src = (const int*)d_in[3];
    const int*  dst = (const int*)d_in[4];
    const float* W1 = (const float*)d_in[5];
    const float* W2 = (const float*)d_in[6];
    float* out = (float*)d_out;

    int N = in_sizes[1] / 32;   // nf is [N, 32]
    int E = in_sizes[3];        // src is [E]

    int ge   = (E + 255) / 256;        // scatter / hist blocks
    int gsc  = (NN + 1023) / 1024;     // 49
    int gpq  = (N + 63) / 64;
    int gf   = (N + 31) / 32;

    hist_kernel<<<ge, 256>>>(dst, W1, W2, E);
    scan1_kernel<<<gsc, 1024>>>();
    scan2_kernel<<<gsc, 1024>>>(E);
    fused4_kernel<<<ge + gpq, 256>>>(src, dst, ef, nf, N, E, ge);
    gather_finalize_kernel<<<gf, 256>>>(h, out, N);
}

// round 15
// speedup vs baseline: 1.3984x; 1.3984x over previous
#include <cuda_runtime.h>

#define NN 50000
#define NE 800000
#define HH 64

// Scratch (no runtime allocation allowed)
__device__ __align__(16) float g_u[NN * HH];      // h @ W1d^T
__device__ __align__(16) float g_p[NN * HH];      // nf @ W1a^T
__device__ __align__(16) float g_q[NN * HH];      // nf @ W1b^T
__device__ __align__(16) float g_efs[NN * 16];    // per-dst ef sums (RED in scatter)

// CSR build scratch
__device__ int  g_cnt[NN];      // zero at load; re-zeroed by scan1 each run
__device__ int  g_off[NN + 1];
__device__ int  g_cur[NN];
__device__ int  g_bsum[64];
__device__ int  g_esrc[NE];     // src, sorted by dst

// Pre-transposed weights (filled by hist_kernel block 0)
__device__ __align__(16) float g_WpqT[32 * 128];  // [k][j]: j<64 -> W1a, j>=64 -> W1b
__device__ __align__(16) float g_WuT[64 * 64];    // [k][j] = W1[j][80+k]
__device__ __align__(16) float g_W1cT[16 * 64];   // [k][j] = W1[j][64+k]
__device__ __align__(16) float g_W2T[64 * 64];    // [j][i] = W2[i][j]

__device__ __forceinline__ void fma4(float4& a, float x, const float4& wv) {
    a.x = fmaf(x, wv.x, a.x);
    a.y = fmaf(x, wv.y, a.y);
    a.z = fmaf(x, wv.z, a.z);
    a.w = fmaf(x, wv.w, a.w);
}

__device__ __forceinline__ void add4(float4& a, const float4& b) {
    a.x += b.x; a.y += b.y; a.z += b.z; a.w += b.w;
}

// ---------------------------------------------------------------------------
// Launch 1: histogram of dst + zero g_efs; block 0 also transposes weights.
// Relies on g_cnt == 0 on entry (zero-init at load; scan1 re-zeroes each run).
// ---------------------------------------------------------------------------
__global__ __launch_bounds__(256) void hist_kernel(
    const int* __restrict__ dst, const float* __restrict__ W1,
    const float* __restrict__ W2, int E)
{
    int tid = blockIdx.x * blockDim.x + threadIdx.x;
    int stride = gridDim.x * blockDim.x;

    float4* efs4 = reinterpret_cast<float4*>(g_efs);
    float4 z = make_float4(0.f, 0.f, 0.f, 0.f);
    for (int i = tid; i < NN * 4; i += stride) efs4[i] = z;

    if (tid < E) atomicAdd(&g_cnt[__ldg(&dst[tid])], 1);

    if (blockIdx.x == 0) {
        for (int idx = threadIdx.x; idx < 64 * 144; idx += 256) {
            int j = idx / 144, k = idx % 144;
            float w = W1[idx];
            if (k < 32)       g_WpqT[k * 128 + j] = w;
            else if (k < 64)  g_WpqT[(k - 32) * 128 + 64 + j] = w;
            else if (k < 80)  g_W1cT[(k - 64) * 64 + j] = w;
            else              g_WuT[(k - 80) * 64 + j] = w;
        }
        for (int idx = threadIdx.x; idx < 64 * 64; idx += 256) {
            int i = idx >> 6, j = idx & 63;
            g_W2T[j * 64 + i] = W2[idx];
        }
    }
}

// ---------------------------------------------------------------------------
// Launch 2: per-1024-chunk exclusive scan + chunk totals; re-zero g_cnt.
// ---------------------------------------------------------------------------
__global__ __launch_bounds__(1024) void scan1_kernel()
{
    __shared__ int s[1024];
    int tid = threadIdx.x;
    int idx = blockIdx.x * 1024 + tid;
    int v = 0;
    if (idx < NN) {
        v = g_cnt[idx];
        g_cnt[idx] = 0;          // reset for next run (graph replay invariant)
    }
    s[tid] = v;
    __syncthreads();
    #pragma unroll
    for (int d = 1; d < 1024; d <<= 1) {
        int t = (tid >= d) ? s[tid - d] : 0;
        __syncthreads();
        s[tid] += t;
        __syncthreads();
    }
    if (idx < NN) g_off[idx] = s[tid] - v;   // exclusive (within chunk)
    if (tid == 1023) g_bsum[blockIdx.x] = s[1023];
}

// ---------------------------------------------------------------------------
// Launch 3: add chunk-prefix; fill g_cur. (Must finish before any scatter.)
// ---------------------------------------------------------------------------
__global__ __launch_bounds__(1024) void scan2_kernel(int E)
{
    int b = blockIdx.x, tid = threadIdx.x;
    int idx = b * 1024 + tid;
    int add = 0;
    for (int j = 0; j < b; j++) add += g_bsum[j];   // uniform, tiny
    if (idx < NN) {
        int v = g_off[idx] + add;
        g_off[idx] = v;
        g_cur[idx] = v;
    }
    if (b == 0 && tid == 0) g_off[NN] = E;
}

// ---------------------------------------------------------------------------
// Launch 4 (striped block-partitioned fusion): scatter | pq GEMM | u GEMM.
// Role assignment is Bresenham-interleaved so every dispatch wave carries a
// ~proportional mix of scatter blocks (latency-bound) and GEMM blocks
// (FMA-bound) — true co-residency per SM, unlike contiguous role ranges.
//   scatter id in [0, gs):    scatter src + RED ef sums
//   gemm id in [0, gpq):      [p|q] = nf @ [W1a^T|W1b^T], 64-node tile
//   gemm id in [gpq, ...):    u = h @ W1d^T, 64-node tile
// ---------------------------------------------------------------------------
__global__ __launch_bounds__(256) void fused4_kernel(
    const int* __restrict__ src, const int* __restrict__ dst,
    const float* __restrict__ ef,
    const float* __restrict__ nf, const float* __restrict__ h,
    int N, int E, int gs, int gpq, int G)
{
    __shared__ __align__(16) char smem_raw[32768];
    int b = blockIdx.x;

    // Bresenham interleave: exact bijection onto scatter ids and gemm ids.
    long long t0 = (long long)b * gs / G;
    long long t1 = (long long)(b + 1) * gs / G;
    bool is_scatter = (t1 > t0);
    int id = is_scatter ? (int)t0 : (int)(b - t0);

    if (is_scatter) {
        // ---- scatter ----
        int i = id * 256 + threadIdx.x;
        if (i >= E) return;
        int d = __ldg(&dst[i]);
        int pos = atomicAdd(&g_cur[d], 1);
        g_esrc[pos] = __ldg(&src[i]);

        const float4* ef4 = reinterpret_cast<const float4*>(ef);
        float4* efs4 = reinterpret_cast<float4*>(g_efs);
        #pragma unroll
        for (int c = 0; c < 4; c++)
            atomicAdd(&efs4[d * 4 + c], __ldg(&ef4[i * 4 + c]));
        return;
    }

    if (id < gpq) {
        // ---- pq GEMM: 64 nodes x 128 outputs, K=32, acc[8] ----
        int bid = id;
        float* sW = reinterpret_cast<float*>(smem_raw);            // 32*128 = 16KB
        float* sX = reinterpret_cast<float*>(smem_raw + 16384);    // 64*32  = 8KB

        for (int idx = threadIdx.x; idx < 32 * 128; idx += 256)
            sW[idx] = g_WpqT[idx];

        int n0 = bid * 64;
        const float4* nf4 = reinterpret_cast<const float4*>(nf);
        float4* sX4 = reinterpret_cast<float4*>(sX);
        for (int idx = threadIdx.x; idx < 512; idx += 256) {
            int n = n0 + (idx >> 3);
            sX4[idx] = (n < N) ? __ldg(&nf4[n * 8 + (idx & 7)])
                               : make_float4(0.f, 0.f, 0.f, 0.f);
        }
        __syncthreads();

        int jg = threadIdx.x & 31;
        int ng = threadIdx.x >> 5;
        const float* xb = sX + ng * 8 * 32;
        const float4* sW4 = reinterpret_cast<const float4*>(sW);

        float4 acc[8];
        #pragma unroll
        for (int i = 0; i < 8; i++) acc[i] = make_float4(0.f, 0.f, 0.f, 0.f);

        #pragma unroll 8
        for (int k = 0; k < 32; k++) {
            float4 wv = sW4[k * 32 + jg];
            #pragma unroll
            for (int i = 0; i < 8; i++) fma4(acc[i], xb[i * 32 + k], wv);
        }

        float4* dst4 = (jg < 16) ? reinterpret_cast<float4*>(g_p)
                                 : reinterpret_cast<float4*>(g_q);
        int jj = jg & 15;
        #pragma unroll
        for (int i = 0; i < 8; i++) {
            int n = n0 + ng * 8 + i;
            if (n < N) dst4[n * 16 + jj] = acc[i];
        }
        return;
    }

    // ---- u GEMM: 64 nodes x 64 outputs, K=64, acc[4] ----
    {
        int bid = id - gpq;
        float* sW = reinterpret_cast<float*>(smem_raw);            // 64*64 = 16KB
        float* sX = reinterpret_cast<float*>(smem_raw + 16384);    // 64*64 = 16KB

        for (int idx = threadIdx.x; idx < 64 * 64; idx += 256)
            sW[idx] = g_WuT[idx];

        int n0 = bid * 64;
        const float4* h4 = reinterpret_cast<const float4*>(h);
        float4* sX4 = reinterpret_cast<float4*>(sX);
        for (int idx = threadIdx.x; idx < 1024; idx += 256) {
            int n = n0 + (idx >> 4);
            sX4[idx] = (n < N) ? __ldg(&h4[n * 16 + (idx & 15)])
                               : make_float4(0.f, 0.f, 0.f, 0.f);
        }
        __syncthreads();

        int jg = threadIdx.x & 15;    // 16 groups x 4 outputs = 64 outputs
        int ng = threadIdx.x >> 4;    // 16 groups x 4 nodes = 64 nodes
        const float* xb = sX + ng * 4 * 64;
        const float4* sW4 = reinterpret_cast<const float4*>(sW);

        float4 acc[4];
        #pragma unroll
        for (int i = 0; i < 4; i++) acc[i] = make_float4(0.f, 0.f, 0.f, 0.f);

        #pragma unroll 8
        for (int k = 0; k < 64; k++) {
            float4 wv = sW4[k * 16 + jg];
            #pragma unroll
            for (int i = 0; i < 4; i++) fma4(acc[i], xb[i * 64 + k], wv);
        }

        float4* du4 = reinterpret_cast<float4*>(g_u);
        #pragma unroll
        for (int i = 0; i < 4; i++) {
            int n = n0 + ng * 4 + i;
            if (n < N) du4[n * 16 + jg] = acc[i];
        }
    }
}

// ---------------------------------------------------------------------------
// Launch 5: fused gather + finalize, 2-way edge-parallel lanes, pure-u loop.
// Warp = 2 edge slots x 16 float4 lanes; unroll 4 pairs (8 edges in flight).
// y = u_sum + p + deg*q + W1c@efs; relu; staged 4-node W2 GEMM.
// ---------------------------------------------------------------------------
__global__ __launch_bounds__(256) void gather_finalize_kernel(
    const float* __restrict__ h, float* __restrict__ out, int N)
{
    __shared__ float sW1cT[16 * 64];
    __shared__ float sW2T[64 * 64];
    __shared__ __align__(16) float sY[8][4 * 64];
    __shared__ float sEf[8][4 * 16];

    for (int idx = threadIdx.x; idx < 16 * 64; idx += 256) sW1cT[idx] = g_W1cT[idx];
    for (int idx = threadIdx.x; idx < 64 * 64; idx += 256) sW2T[idx]  = g_W2T[idx];
    __syncthreads();

    int lane = threadIdx.x & 31;
    int warp = threadIdx.x >> 5;
    int slot = lane >> 4;          // 0 or 1
    int f4   = lane & 15;          // float4 index within 64-float row
    int gw = (blockIdx.x * blockDim.x + threadIdx.x) >> 5;
    int nb = gw * 4;
    if (nb >= N) return;
    int cnt = min(4, N - nb);

    const float4* u4 = reinterpret_cast<const float4*>(g_u);
    float dgv[4];

    for (int m = 0; m < cnt; m++) {
        int n = nb + m;
        int off0 = __ldg(&g_off[n]);
        int off1 = __ldg(&g_off[n + 1]);
        dgv[m] = (float)(off1 - off0);

        float4 acc = make_float4(0.f, 0.f, 0.f, 0.f);

        int i = off0;
        for (; i + 8 <= off1; i += 8) {
            int sA = __ldg(&g_esrc[i     + slot]);
            int sB = __ldg(&g_esrc[i + 2 + slot]);
            int sC = __ldg(&g_esrc[i + 4 + slot]);
            int sD = __ldg(&g_esrc[i + 6 + slot]);
            float4 vA = __ldg(&u4[sA * 16 + f4]);
            float4 vB = __ldg(&u4[sB * 16 + f4]);
            float4 vC = __ldg(&u4[sC * 16 + f4]);
            float4 vD = __ldg(&u4[sD * 16 + f4]);
            add4(acc, vA); add4(acc, vB); add4(acc, vC); add4(acc, vD);
        }
        for (; i + 2 <= off1; i += 2) {
            int s = __ldg(&g_esrc[i + slot]);
            float4 v = __ldg(&u4[s * 16 + f4]);
            add4(acc, v);
        }
        if (i < off1 && slot == 0) {   // odd remainder: slot-0 lanes only
            int s = __ldg(&g_esrc[i]);
            float4 v = __ldg(&u4[s * 16 + f4]);
            add4(acc, v);
        }

        // merge slot 0 + slot 1
        acc.x += __shfl_xor_sync(0xffffffffu, acc.x, 16);
        acc.y += __shfl_xor_sync(0xffffffffu, acc.y, 16);
        acc.z += __shfl_xor_sync(0xffffffffu, acc.z, 16);
        acc.w += __shfl_xor_sync(0xffffffffu, acc.w, 16);

        if (lane < 16) {
            reinterpret_cast<float4*>(&sY[warp][m * 64])[f4] = acc;
            sEf[warp][m * 16 + lane] = __ldg(&g_efs[n * 16 + lane]);
        }
        __syncwarp();

        float dg = dgv[m];
        float y0 = sY[warp][m * 64 + lane]
                 + g_p[n * 64 + lane]      + dg * g_q[n * 64 + lane];
        float y1 = sY[warp][m * 64 + lane + 32]
                 + g_p[n * 64 + lane + 32] + dg * g_q[n * 64 + lane + 32];

        #pragma unroll
        for (int k = 0; k < 16; k++) {
            float mk = sEf[warp][m * 16 + k];
            y0 = fmaf(mk, sW1cT[k * 64 + lane],      y0);
            y1 = fmaf(mk, sW1cT[k * 64 + lane + 32], y1);
        }
        sY[warp][m * 64 + lane]      = fmaxf(y0, 0.f);
        sY[warp][m * 64 + lane + 32] = fmaxf(y1, 0.f);
    }
    __syncwarp();

    float o0[4] = {0.f, 0.f, 0.f, 0.f};
    float o1[4] = {0.f, 0.f, 0.f, 0.f};
    #pragma unroll
    for (int j = 0; j < 64; j++) {
        float w0 = sW2T[j * 64 + lane];
        float w1 = sW2T[j * 64 + lane + 32];
        #pragma unroll
        for (int m = 0; m < 4; m++) {
            float yj = sY[warp][m * 64 + j];
            o0[m] = fmaf(yj, w0, o0[m]);
            o1[m] = fmaf(yj, w1, o1[m]);
        }
    }

    for (int m = 0; m < cnt; m++) {
        int n = nb + m;
        if (dgv[m] > 0.f) {
            out[n * 64 + lane]      = o0[m];
            out[n * 64 + lane + 32] = o1[m];
        } else {
            out[n * 64 + lane]      = h[n * 64 + lane];
            out[n * 64 + lane + 32] = h[n * 64 + lane + 32];
        }
    }
}

// ---------------------------------------------------------------------------
extern "C" void kernel_launch(void* const* d_in, const int* in_sizes, int n_in,
                              void* d_out, int out_size)
{
    const float* h  = (const float*)d_in[0];
    const float* nf = (const float*)d_in[1];
    const float* ef = (const float*)d_in[2];
    const int*  src = (const int*)d_in[3];
    const int*  dst = (const int*)d_in[4];
    const float* W1 = (const float*)d_in[5];
    const float* W2 = (const float*)d_in[6];
    float* out = (float*)d_out;

    int N = in_sizes[1] / 32;   // nf is [N, 32]
    int E = in_sizes[3];        // src is [E]

    int ge   = (E + 255) / 256;        // scatter blocks
    int gsc  = (NN + 1023) / 1024;     // 49
    int gpq  = (N + 63) / 64;
    int gu   = (N + 63) / 64;
    int gf   = (N + 31) / 32;
    int G    = ge + gpq + gu;

    hist_kernel<<<ge, 256>>>(dst, W1, W2, E);
    scan1_kernel<<<gsc, 1024>>>();
    scan2_kernel<<<gsc, 1024>>>(E);
    fused4_kernel<<<G, 256>>>(src, dst, ef, nf, h, N, E, ge, gpq, G);
    gather_finalize_kernel<<<gf, 256>>>(h, out, N);
}